// round 7
// baseline (speedup 1.0000x reference)
#include <cuda_runtime.h>
#include <cuda_bf16.h>
#include <cstdint>

// GlobalAggregator: B=256, N=256, K=16, DIM=128
// 1 bn per warp; n-dim processed in two halves (8 n-tiles each) to halve accumulator
// pressure (64->32 regs), freeing registers for explicit next-kc prefetch of the
// neighbor loads (hides LDG latency; A rebuilt on 2nd half from L1-hot lines).
//   A[16x128] = extra[bn] * neighbor[bn]  -> bf16 hi/lo frags in registers
//   Bt[e][d] = w1[d][e] hi/lo in SMEM, read via ldmatrix
//   D = A @ Bt^T via mma.sync bf16 x3, fp32 accum
//   epilogue warp-local: z=D+wk*bias; leaky(0.2); dot w2; softmax(16); out=sum alpha*nb

#define DIMX 128
#define KN   16
#define NTHREADS 256
#define BSTRIDE 272          // bytes per Bt row (128 bf16 + 8 pad)

#define SM_B1   0            // 128 x 272 = 34816
#define SM_B2   34816
#define SM_BIAS 69632        // 128 f32
#define SM_W2   70144        // 128 f32
#define SM_TOTAL 70656

static __device__ __forceinline__ uint32_t smem_u32(const void* p) {
    uint32_t a;
    asm("{ .reg .u64 t; cvta.to.shared.u64 t, %1; cvt.u32.u64 %0, t; }" : "=r"(a) : "l"(p));
    return a;
}
static __device__ __forceinline__ void ldsm4(uint32_t& r0, uint32_t& r1, uint32_t& r2, uint32_t& r3,
                                             uint32_t addr) {
    asm volatile("ldmatrix.sync.aligned.m8n8.x4.shared.b16 {%0,%1,%2,%3}, [%4];"
                 : "=r"(r0), "=r"(r1), "=r"(r2), "=r"(r3) : "r"(addr));
}
static __device__ __forceinline__ void mma_bf16(float& c0, float& c1, float& c2, float& c3,
                                                uint32_t a0, uint32_t a1, uint32_t a2, uint32_t a3,
                                                uint32_t b0, uint32_t b1) {
    asm volatile("mma.sync.aligned.m16n8k16.row.col.f32.bf16.bf16.f32 "
                 "{%0,%1,%2,%3},{%4,%5,%6,%7},{%8,%9},{%0,%1,%2,%3};"
                 : "+f"(c0), "+f"(c1), "+f"(c2), "+f"(c3)
                 : "r"(a0), "r"(a1), "r"(a2), "r"(a3), "r"(b0), "r"(b1));
}
static __device__ __forceinline__ uint32_t pack_hi(float x, float y) {
    __nv_bfloat162 h(__float2bfloat16(x), __float2bfloat16(y));
    return *(uint32_t*)&h;
}
static __device__ __forceinline__ uint32_t pack_lo(float x, float y, uint32_t hi) {
    __nv_bfloat162 h = *(__nv_bfloat162*)&hi;
    __nv_bfloat162 l(__float2bfloat16(x - __bfloat162float(h.x)),
                     __float2bfloat16(y - __bfloat162float(h.y)));
    return *(uint32_t*)&l;
}
__device__ __forceinline__ float leaky02(float v) { return v > 0.0f ? v : 0.2f * v; }

extern "C" __global__ void __launch_bounds__(NTHREADS, 2)
agg_mma_kernel(const float* __restrict__ neighbor,
               const float* __restrict__ nweight,
               const float* __restrict__ extra,
               const float* __restrict__ w1,
               const float* __restrict__ w2,
               float* __restrict__ out,
               int total_bn)
{
    extern __shared__ __align__(16) char smem[];
    const uint32_t sbase = smem_u32(smem);
    const int tid  = threadIdx.x;
    const int warp = tid >> 5;
    const int lane = tid & 31;

    float* biass = (float*)(smem + SM_BIAS);
    float* w2s   = (float*)(smem + SM_W2);

    // ---- build Bt (w1 transposed) hi/lo once per block ----
    for (int idx = tid; idx < DIMX * DIMX; idx += NTHREADS) {
        int d = idx >> 7;
        int e = idx & 127;
        float v = w1[idx];
        __nv_bfloat16 hb = __float2bfloat16(v);
        __nv_bfloat16 lb = __float2bfloat16(v - __bfloat162float(hb));
        uint32_t off = (uint32_t)e * BSTRIDE + (uint32_t)d * 2;
        *(__nv_bfloat16*)(smem + SM_B1 + off) = hb;
        *(__nv_bfloat16*)(smem + SM_B2 + off) = lb;
    }
    if (tid < DIMX) {
        biass[tid] = w1[DIMX * DIMX + tid];
        w2s[tid]   = w2[tid];
    }
    __syncthreads();

    const uint32_t b_base = sbase + ((lane & 7) + ((lane >> 4) & 1) * 8) * BSTRIDE
                          + ((lane >> 3) & 1) * 16;

    const int g  = lane >> 2;          // row group 0..7
    const int i2 = (lane & 3) * 2;     // col pair base

    const int gwarp   = blockIdx.x * 8 + warp;
    const int gstride = gridDim.x * 8;

    for (int bn = gwarp; bn < total_bn; bn += gstride) {
        const float* nbase = neighbor + (size_t)bn * (KN * DIMX);
        const float* ebase = extra + (size_t)bn * DIMX;

        const float wk0 = nweight[(size_t)bn * KN + g];
        const float wk1 = nweight[(size_t)bn * KN + g + 8];

        float p0 = 0.f, p1 = 0.f;

        #pragma unroll
        for (int half = 0; half < 2; ++half) {
            float c[8][4];
            #pragma unroll
            for (int nt = 0; nt < 8; ++nt)
                { c[nt][0]=0.f; c[nt][1]=0.f; c[nt][2]=0.f; c[nt][3]=0.f; }

            // prefetch kc=0 neighbor loads
            float2 pn00 = *(const float2*)(nbase + g * DIMX + i2);
            float2 pn10 = *(const float2*)(nbase + (g + 8) * DIMX + i2);
            float2 pn01 = *(const float2*)(nbase + g * DIMX + i2 + 8);
            float2 pn11 = *(const float2*)(nbase + (g + 8) * DIMX + i2 + 8);

            #pragma unroll
            for (int kc = 0; kc < 8; ++kc) {
                const int c0 = kc * 16 + i2;
                float2 n00 = pn00, n10 = pn10, n01 = pn01, n11 = pn11;
                if (kc < 7) {           // prefetch next kc
                    const int c1 = c0 + 16;
                    pn00 = *(const float2*)(nbase + g * DIMX + c1);
                    pn10 = *(const float2*)(nbase + (g + 8) * DIMX + c1);
                    pn01 = *(const float2*)(nbase + g * DIMX + c1 + 8);
                    pn11 = *(const float2*)(nbase + (g + 8) * DIMX + c1 + 8);
                }
                float2 e0 = *(const float2*)(ebase + c0);
                float2 e1 = *(const float2*)(ebase + c0 + 8);

                float g00x = n00.x * e0.x, g00y = n00.y * e0.y;
                float g10x = n10.x * e0.x, g10y = n10.y * e0.y;
                float g01x = n01.x * e1.x, g01y = n01.y * e1.y;
                float g11x = n11.x * e1.x, g11y = n11.y * e1.y;

                uint32_t ah0 = pack_hi(g00x, g00y), ah1 = pack_hi(g10x, g10y);
                uint32_t ah2 = pack_hi(g01x, g01y), ah3 = pack_hi(g11x, g11y);
                uint32_t al0 = pack_lo(g00x, g00y, ah0), al1 = pack_lo(g10x, g10y, ah1);
                uint32_t al2 = pack_lo(g01x, g01y, ah2), al3 = pack_lo(g11x, g11y, ah3);

                #pragma unroll
                for (int np = 0; np < 4; ++np) {
                    uint32_t bh0, bh1, bh2, bh3, bl0, bl1, bl2, bl3;
                    uint32_t boff = (uint32_t)((half * 4 + np) * 16) * BSTRIDE + kc * 32;
                    ldsm4(bh0, bh1, bh2, bh3, b_base + SM_B1 + boff);
                    ldsm4(bl0, bl1, bl2, bl3, b_base + SM_B2 + boff);
                    float* cA = c[2 * np];
                    float* cB = c[2 * np + 1];
                    mma_bf16(cA[0], cA[1], cA[2], cA[3], ah0, ah1, ah2, ah3, bh0, bh1);
                    mma_bf16(cB[0], cB[1], cB[2], cB[3], ah0, ah1, ah2, ah3, bh2, bh3);
                    mma_bf16(cA[0], cA[1], cA[2], cA[3], ah0, ah1, ah2, ah3, bl0, bl1);
                    mma_bf16(cB[0], cB[1], cB[2], cB[3], ah0, ah1, ah2, ah3, bl2, bl3);
                    mma_bf16(cA[0], cA[1], cA[2], cA[3], al0, al1, al2, al3, bh0, bh1);
                    mma_bf16(cB[0], cB[1], cB[2], cB[3], al0, al1, al2, al3, bh2, bh3);
                }
            }

            // partial epilogue for this half: bias + leaky + w2 dot
            #pragma unroll
            for (int nt = 0; nt < 8; ++nt) {
                int e0i = (half * 8 + nt) * 8 + i2;
                float b0 = biass[e0i], b1 = biass[e0i + 1];
                float v0 = w2s[e0i],  v1 = w2s[e0i + 1];
                p0 = fmaf(leaky02(c[nt][0] + wk0 * b0), v0, p0);
                p0 = fmaf(leaky02(c[nt][1] + wk0 * b1), v1, p0);
                p1 = fmaf(leaky02(c[nt][2] + wk1 * b0), v0, p1);
                p1 = fmaf(leaky02(c[nt][3] + wk1 * b1), v1, p1);
            }
        }

        // ---- reductions + softmax (warp-local) ----
        p0 += __shfl_xor_sync(0xffffffffu, p0, 1);
        p0 += __shfl_xor_sync(0xffffffffu, p0, 2);
        p1 += __shfl_xor_sync(0xffffffffu, p1, 1);
        p1 += __shfl_xor_sync(0xffffffffu, p1, 2);

        float mx = fmaxf(p0, p1);
        #pragma unroll
        for (int o = 4; o <= 16; o <<= 1)
            mx = fmaxf(mx, __shfl_xor_sync(0xffffffffu, mx, o));
        float e0v = __expf(p0 - mx);
        float e1v = __expf(p1 - mx);
        float s = e0v + e1v;
        #pragma unroll
        for (int o = 4; o <= 16; o <<= 1)
            s += __shfl_xor_sync(0xffffffffu, s, o);
        float a0n = e0v / s;
        float a1n = e1v / s;

        float al2[KN];
        #pragma unroll
        for (int k = 0; k < 8; ++k)  al2[k]     = __shfl_sync(0xffffffffu, a0n, k << 2);
        #pragma unroll
        for (int k = 0; k < 8; ++k)  al2[k + 8] = __shfl_sync(0xffffffffu, a1n, k << 2);

        // ---- out[bn][d] = sum_k alpha[k] * neighbor[bn][k][d]  (L1/L2 hot) ----
        {
            const float4* nb4 = (const float4*)nbase + lane;
            float4 acc = make_float4(0.f, 0.f, 0.f, 0.f);
            #pragma unroll
            for (int k = 0; k < KN; ++k) {
                float4 nv = nb4[k * 32];
                acc.x = fmaf(al2[k], nv.x, acc.x);
                acc.y = fmaf(al2[k], nv.y, acc.y);
                acc.z = fmaf(al2[k], nv.z, acc.z);
                acc.w = fmaf(al2[k], nv.w, acc.w);
            }
            ((float4*)(out + (size_t)bn * DIMX))[lane] = acc;
        }
    }
}

extern "C" void kernel_launch(void* const* d_in, const int* in_sizes, int n_in,
                              void* d_out, int out_size) {
    const float* neighbor = (const float*)d_in[1];
    const float* nweight  = (const float*)d_in[4];
    const float* extra    = (const float*)d_in[5];
    const float* w1       = (const float*)d_in[6];
    const float* w2       = (const float*)d_in[7];
    float* out            = (float*)d_out;

    const int total_bn = in_sizes[5] / DIMX;   // 65536

    cudaFuncSetAttribute(agg_mma_kernel, cudaFuncAttributeMaxDynamicSharedMemorySize, SM_TOTAL);
    agg_mma_kernel<<<304, NTHREADS, SM_TOTAL>>>(neighbor, nweight, extra, w1, w2, out, total_bn);
}

// round 8
// speedup vs baseline: 1.3574x; 1.3574x over previous
#include <cuda_runtime.h>
#include <cuda_fp16.h>
#include <cstdint>

// GlobalAggregator: B=256, N=256, K=16, DIM=128
// fp16 2-term scheme: A = ah + al (fp16 hi/lo, exact to ~2^-22), B single fp16 (~2^-11).
//   z = (ah + al) @ Bt^T  via mma.sync m16n8k16 f32.f16.f16.f32, fp32 accum
// Per np-pair: ONE ldsm4 for B + 4 MMAs (vs 2 ldsm + 6 MMA for bf16x3).
// 1 bn per warp, fully warp-local epilogue (R5 structure).

#define DIMX 128
#define KN   16
#define NTHREADS 256
#define BSTRIDE 272          // bytes per Bt row (128 fp16 + 8 pad) -> conflict-free ldmatrix

#define SM_B1   0            // 128 x 272 = 34816
#define SM_BIAS 34816        // 128 f32
#define SM_W2   35328        // 128 f32
#define SM_TOTAL 35840

static __device__ __forceinline__ uint32_t smem_u32(const void* p) {
    uint32_t a;
    asm("{ .reg .u64 t; cvta.to.shared.u64 t, %1; cvt.u32.u64 %0, t; }" : "=r"(a) : "l"(p));
    return a;
}
static __device__ __forceinline__ void ldsm4(uint32_t& r0, uint32_t& r1, uint32_t& r2, uint32_t& r3,
                                             uint32_t addr) {
    asm volatile("ldmatrix.sync.aligned.m8n8.x4.shared.b16 {%0,%1,%2,%3}, [%4];"
                 : "=r"(r0), "=r"(r1), "=r"(r2), "=r"(r3) : "r"(addr));
}
static __device__ __forceinline__ void mma_f16(float& c0, float& c1, float& c2, float& c3,
                                               uint32_t a0, uint32_t a1, uint32_t a2, uint32_t a3,
                                               uint32_t b0, uint32_t b1) {
    asm volatile("mma.sync.aligned.m16n8k16.row.col.f32.f16.f16.f32 "
                 "{%0,%1,%2,%3},{%4,%5,%6,%7},{%8,%9},{%0,%1,%2,%3};"
                 : "+f"(c0), "+f"(c1), "+f"(c2), "+f"(c3)
                 : "r"(a0), "r"(a1), "r"(a2), "r"(a3), "r"(b0), "r"(b1));
}
static __device__ __forceinline__ uint32_t pack_hi(float x, float y) {
    __half2 h(__float2half_rn(x), __float2half_rn(y));
    return *(uint32_t*)&h;
}
static __device__ __forceinline__ uint32_t pack_lo(float x, float y, uint32_t hi) {
    __half2 h = *(__half2*)&hi;
    __half2 l(__float2half_rn(x - __half2float(h.x)),
              __float2half_rn(y - __half2float(h.y)));
    return *(uint32_t*)&l;
}
__device__ __forceinline__ float leaky02(float v) { return v > 0.0f ? v : 0.2f * v; }

extern "C" __global__ void __launch_bounds__(NTHREADS, 2)
agg_mma_kernel(const float* __restrict__ neighbor,
               const float* __restrict__ nweight,
               const float* __restrict__ extra,
               const float* __restrict__ w1,
               const float* __restrict__ w2,
               float* __restrict__ out,
               int total_bn)
{
    extern __shared__ __align__(16) char smem[];
    const uint32_t sbase = smem_u32(smem);
    const int tid  = threadIdx.x;
    const int warp = tid >> 5;
    const int lane = tid & 31;

    float* biass = (float*)(smem + SM_BIAS);
    float* w2s   = (float*)(smem + SM_W2);

    // ---- build Bt (w1 transposed, single fp16) once per block ----
    for (int idx = tid; idx < DIMX * DIMX; idx += NTHREADS) {
        int d = idx >> 7;          // reduction dim (w1 row)
        int e = idx & 127;         // output dim  (w1 col) -> Bt row
        uint32_t off = (uint32_t)e * BSTRIDE + (uint32_t)d * 2;
        *(__half*)(smem + SM_B1 + off) = __float2half_rn(w1[idx]);
    }
    if (tid < DIMX) {
        biass[tid] = w1[DIMX * DIMX + tid];
        w2s[tid]   = w2[tid];
    }
    __syncthreads();

    // B ldmatrix lane addressing: rows (lane&7)+((lane>>4)&1)*8, 16B col sel (lane>>3)&1
    const uint32_t b_base = sbase + SM_B1
                          + ((lane & 7) + ((lane >> 4) & 1) * 8) * BSTRIDE
                          + ((lane >> 3) & 1) * 16;

    const int g  = lane >> 2;          // row group 0..7
    const int i2 = (lane & 3) * 2;     // col pair base

    const int gwarp   = blockIdx.x * 8 + warp;
    const int gstride = gridDim.x * 8;

    for (int bn = gwarp; bn < total_bn; bn += gstride) {
        const float* nbase = neighbor + (size_t)bn * (KN * DIMX);
        const float* ebase = extra + (size_t)bn * DIMX;

        // ---- GEMM: C[16 k-rows][128 e], A frags straight from global ----
        float c[16][4];
        #pragma unroll
        for (int nt = 0; nt < 16; ++nt) { c[nt][0]=0.f; c[nt][1]=0.f; c[nt][2]=0.f; c[nt][3]=0.f; }

        #pragma unroll
        for (int kc = 0; kc < 8; ++kc) {
            const int c0 = kc * 16 + i2;
            float2 n00 = *(const float2*)(nbase + g * DIMX + c0);
            float2 n10 = *(const float2*)(nbase + (g + 8) * DIMX + c0);
            float2 n01 = *(const float2*)(nbase + g * DIMX + c0 + 8);
            float2 n11 = *(const float2*)(nbase + (g + 8) * DIMX + c0 + 8);
            float2 e0  = *(const float2*)(ebase + c0);
            float2 e1  = *(const float2*)(ebase + c0 + 8);

            float g00x = n00.x * e0.x, g00y = n00.y * e0.y;
            float g10x = n10.x * e0.x, g10y = n10.y * e0.y;
            float g01x = n01.x * e1.x, g01y = n01.y * e1.y;
            float g11x = n11.x * e1.x, g11y = n11.y * e1.y;

            uint32_t ah0 = pack_hi(g00x, g00y), ah1 = pack_hi(g10x, g10y);
            uint32_t ah2 = pack_hi(g01x, g01y), ah3 = pack_hi(g11x, g11y);
            uint32_t al0 = pack_lo(g00x, g00y, ah0), al1 = pack_lo(g10x, g10y, ah1);
            uint32_t al2 = pack_lo(g01x, g01y, ah2), al3 = pack_lo(g11x, g11y, ah3);

            #pragma unroll
            for (int np = 0; np < 8; ++np) {       // two 8-wide n-tiles per iter
                uint32_t bh0, bh1, bh2, bh3;
                uint32_t boff = (uint32_t)(np * 16) * BSTRIDE + kc * 32;
                ldsm4(bh0, bh1, bh2, bh3, b_base + boff);
                float* cA = c[2 * np];
                float* cB = c[2 * np + 1];
                mma_f16(cA[0], cA[1], cA[2], cA[3], ah0, ah1, ah2, ah3, bh0, bh1);
                mma_f16(cB[0], cB[1], cB[2], cB[3], ah0, ah1, ah2, ah3, bh2, bh3);
                mma_f16(cA[0], cA[1], cA[2], cA[3], al0, al1, al2, al3, bh0, bh1);
                mma_f16(cB[0], cB[1], cB[2], cB[3], al0, al1, al2, al3, bh2, bh3);
            }
        }

        // ---- epilogue (warp-local) ----
        const float wk0 = nweight[(size_t)bn * KN + g];
        const float wk1 = nweight[(size_t)bn * KN + g + 8];

        float p0 = 0.f, p1 = 0.f;
        #pragma unroll
        for (int nt = 0; nt < 16; ++nt) {
            int e0i = nt * 8 + i2;
            float b0 = biass[e0i], b1 = biass[e0i + 1];
            float v0 = w2s[e0i],  v1 = w2s[e0i + 1];
            p0 = fmaf(leaky02(c[nt][0] + wk0 * b0), v0, p0);
            p0 = fmaf(leaky02(c[nt][1] + wk0 * b1), v1, p0);
            p1 = fmaf(leaky02(c[nt][2] + wk1 * b0), v0, p1);
            p1 = fmaf(leaky02(c[nt][3] + wk1 * b1), v1, p1);
        }
        p0 += __shfl_xor_sync(0xffffffffu, p0, 1);
        p0 += __shfl_xor_sync(0xffffffffu, p0, 2);
        p1 += __shfl_xor_sync(0xffffffffu, p1, 1);
        p1 += __shfl_xor_sync(0xffffffffu, p1, 2);

        // softmax over 16 k (k=g in p0, k=g+8 in p1); dup within quads is fine
        float mx = fmaxf(p0, p1);
        #pragma unroll
        for (int o = 4; o <= 16; o <<= 1)
            mx = fmaxf(mx, __shfl_xor_sync(0xffffffffu, mx, o));
        float e0v = __expf(p0 - mx);
        float e1v = __expf(p1 - mx);
        float s = e0v + e1v;
        #pragma unroll
        for (int o = 4; o <= 16; o <<= 1)
            s += __shfl_xor_sync(0xffffffffu, s, o);
        float a0n = e0v / s;
        float a1n = e1v / s;

        // broadcast alpha[k] via shfl (source lane 4*(k&7))
        float al2[KN];
        #pragma unroll
        for (int k = 0; k < 8; ++k)  al2[k]     = __shfl_sync(0xffffffffu, a0n, k << 2);
        #pragma unroll
        for (int k = 0; k < 8; ++k)  al2[k + 8] = __shfl_sync(0xffffffffu, a1n, k << 2);

        // ---- out[bn][d] = sum_k alpha[k] * neighbor[bn][k][d]  (re-read, L2 hot) ----
        {
            const float4* nb4 = (const float4*)nbase + lane;
            float4 acc = make_float4(0.f, 0.f, 0.f, 0.f);
            #pragma unroll
            for (int k = 0; k < KN; ++k) {
                float4 nv = nb4[k * 32];
                acc.x = fmaf(al2[k], nv.x, acc.x);
                acc.y = fmaf(al2[k], nv.y, acc.y);
                acc.z = fmaf(al2[k], nv.z, acc.z);
                acc.w = fmaf(al2[k], nv.w, acc.w);
            }
            ((float4*)(out + (size_t)bn * DIMX))[lane] = acc;
        }
    }
}

extern "C" void kernel_launch(void* const* d_in, const int* in_sizes, int n_in,
                              void* d_out, int out_size) {
    const float* neighbor = (const float*)d_in[1];
    const float* nweight  = (const float*)d_in[4];
    const float* extra    = (const float*)d_in[5];
    const float* w1       = (const float*)d_in[6];
    const float* w2       = (const float*)d_in[7];
    float* out            = (float*)d_out;

    const int total_bn = in_sizes[5] / DIMX;   // 65536

    cudaFuncSetAttribute(agg_mma_kernel, cudaFuncAttributeMaxDynamicSharedMemorySize, SM_TOTAL);
    agg_mma_kernel<<<304, NTHREADS, SM_TOTAL>>>(neighbor, nweight, extra, w1, w2, out, total_bn);
}

// round 9
// speedup vs baseline: 1.5237x; 1.1225x over previous
#include <cuda_runtime.h>
#include <cuda_fp16.h>
#include <cstdint>

// GlobalAggregator: B=256, N=256, K=16, DIM=128
// Single-term fp16 scheme: A fp16, B fp16, fp32 accum (error ~8e-5 << 1e-3).
//   z = A @ Bt^T via mma.sync m16n8k16 f32.f16.f16.f32
// Per np-pair: ONE ldsm4 for B + 2 MMAs. 128 MMAs per bn.
// 1 bn per warp, warp-local epilogue; next-kc register prefetch of A loads.

#define DIMX 128
#define KN   16
#define NTHREADS 256
#define BSTRIDE 272          // bytes per Bt row (128 fp16 + 8 pad) -> conflict-free ldmatrix

#define SM_B1   0            // 128 x 272 = 34816
#define SM_BIAS 34816        // 128 f32
#define SM_W2   35328        // 128 f32
#define SM_TOTAL 35840

static __device__ __forceinline__ uint32_t smem_u32(const void* p) {
    uint32_t a;
    asm("{ .reg .u64 t; cvta.to.shared.u64 t, %1; cvt.u32.u64 %0, t; }" : "=r"(a) : "l"(p));
    return a;
}
static __device__ __forceinline__ void ldsm4(uint32_t& r0, uint32_t& r1, uint32_t& r2, uint32_t& r3,
                                             uint32_t addr) {
    asm volatile("ldmatrix.sync.aligned.m8n8.x4.shared.b16 {%0,%1,%2,%3}, [%4];"
                 : "=r"(r0), "=r"(r1), "=r"(r2), "=r"(r3) : "r"(addr));
}
static __device__ __forceinline__ void mma_f16(float& c0, float& c1, float& c2, float& c3,
                                               uint32_t a0, uint32_t a1, uint32_t a2, uint32_t a3,
                                               uint32_t b0, uint32_t b1) {
    asm volatile("mma.sync.aligned.m16n8k16.row.col.f32.f16.f16.f32 "
                 "{%0,%1,%2,%3},{%4,%5,%6,%7},{%8,%9},{%0,%1,%2,%3};"
                 : "+f"(c0), "+f"(c1), "+f"(c2), "+f"(c3)
                 : "r"(a0), "r"(a1), "r"(a2), "r"(a3), "r"(b0), "r"(b1));
}
static __device__ __forceinline__ uint32_t pack_h2(float x, float y) {
    __half2 h(__float2half_rn(x), __float2half_rn(y));
    return *(uint32_t*)&h;
}
__device__ __forceinline__ float leaky02(float v) { return v > 0.0f ? v : 0.2f * v; }

extern "C" __global__ void __launch_bounds__(NTHREADS, 2)
agg_mma_kernel(const float* __restrict__ neighbor,
               const float* __restrict__ nweight,
               const float* __restrict__ extra,
               const float* __restrict__ w1,
               const float* __restrict__ w2,
               float* __restrict__ out,
               int total_bn)
{
    extern __shared__ __align__(16) char smem[];
    const uint32_t sbase = smem_u32(smem);
    const int tid  = threadIdx.x;
    const int warp = tid >> 5;
    const int lane = tid & 31;

    float* biass = (float*)(smem + SM_BIAS);
    float* w2s   = (float*)(smem + SM_W2);

    // ---- build Bt (w1 transposed, fp16) once per block ----
    for (int idx = tid; idx < DIMX * DIMX; idx += NTHREADS) {
        int d = idx >> 7;          // reduction dim (w1 row)
        int e = idx & 127;         // output dim  (w1 col) -> Bt row
        uint32_t off = (uint32_t)e * BSTRIDE + (uint32_t)d * 2;
        *(__half*)(smem + SM_B1 + off) = __float2half_rn(w1[idx]);
    }
    if (tid < DIMX) {
        biass[tid] = w1[DIMX * DIMX + tid];
        w2s[tid]   = w2[tid];
    }
    __syncthreads();

    // B ldmatrix lane addressing: rows (lane&7)+((lane>>4)&1)*8, 16B col sel (lane>>3)&1
    const uint32_t b_base = sbase + SM_B1
                          + ((lane & 7) + ((lane >> 4) & 1) * 8) * BSTRIDE
                          + ((lane >> 3) & 1) * 16;

    const int g  = lane >> 2;          // row group 0..7
    const int i2 = (lane & 3) * 2;     // col pair base

    const int gwarp   = blockIdx.x * 8 + warp;
    const int gstride = gridDim.x * 8;

    for (int bn = gwarp; bn < total_bn; bn += gstride) {
        const float* nbase = neighbor + (size_t)bn * (KN * DIMX);
        const float* ebase = extra + (size_t)bn * DIMX;

        float c[16][4];
        #pragma unroll
        for (int nt = 0; nt < 16; ++nt) { c[nt][0]=0.f; c[nt][1]=0.f; c[nt][2]=0.f; c[nt][3]=0.f; }

        // prefetch kc=0 A loads
        float2 pn00 = *(const float2*)(nbase + g * DIMX + i2);
        float2 pn10 = *(const float2*)(nbase + (g + 8) * DIMX + i2);
        float2 pn01 = *(const float2*)(nbase + g * DIMX + i2 + 8);
        float2 pn11 = *(const float2*)(nbase + (g + 8) * DIMX + i2 + 8);
        float2 pe0  = *(const float2*)(ebase + i2);
        float2 pe1  = *(const float2*)(ebase + i2 + 8);

        #pragma unroll
        for (int kc = 0; kc < 8; ++kc) {
            float2 n00 = pn00, n10 = pn10, n01 = pn01, n11 = pn11;
            float2 e0 = pe0, e1 = pe1;
            if (kc < 7) {               // prefetch next kc
                const int c1 = (kc + 1) * 16 + i2;
                pn00 = *(const float2*)(nbase + g * DIMX + c1);
                pn10 = *(const float2*)(nbase + (g + 8) * DIMX + c1);
                pn01 = *(const float2*)(nbase + g * DIMX + c1 + 8);
                pn11 = *(const float2*)(nbase + (g + 8) * DIMX + c1 + 8);
                pe0  = *(const float2*)(ebase + c1);
                pe1  = *(const float2*)(ebase + c1 + 8);
            }

            uint32_t a0 = pack_h2(n00.x * e0.x, n00.y * e0.y);
            uint32_t a1 = pack_h2(n10.x * e0.x, n10.y * e0.y);
            uint32_t a2 = pack_h2(n01.x * e1.x, n01.y * e1.y);
            uint32_t a3 = pack_h2(n11.x * e1.x, n11.y * e1.y);

            #pragma unroll
            for (int np = 0; np < 8; ++np) {       // two 8-wide n-tiles per iter
                uint32_t bh0, bh1, bh2, bh3;
                uint32_t boff = (uint32_t)(np * 16) * BSTRIDE + kc * 32;
                ldsm4(bh0, bh1, bh2, bh3, b_base + boff);
                float* cA = c[2 * np];
                float* cB = c[2 * np + 1];
                mma_f16(cA[0], cA[1], cA[2], cA[3], a0, a1, a2, a3, bh0, bh1);
                mma_f16(cB[0], cB[1], cB[2], cB[3], a0, a1, a2, a3, bh2, bh3);
            }
        }

        // ---- epilogue (warp-local) ----
        const float wk0 = nweight[(size_t)bn * KN + g];
        const float wk1 = nweight[(size_t)bn * KN + g + 8];

        float p0 = 0.f, p1 = 0.f;
        #pragma unroll
        for (int nt = 0; nt < 16; ++nt) {
            int e0i = nt * 8 + i2;
            float b0 = biass[e0i], b1 = biass[e0i + 1];
            float v0 = w2s[e0i],  v1 = w2s[e0i + 1];
            p0 = fmaf(leaky02(c[nt][0] + wk0 * b0), v0, p0);
            p0 = fmaf(leaky02(c[nt][1] + wk0 * b1), v1, p0);
            p1 = fmaf(leaky02(c[nt][2] + wk1 * b0), v0, p1);
            p1 = fmaf(leaky02(c[nt][3] + wk1 * b1), v1, p1);
        }
        p0 += __shfl_xor_sync(0xffffffffu, p0, 1);
        p0 += __shfl_xor_sync(0xffffffffu, p0, 2);
        p1 += __shfl_xor_sync(0xffffffffu, p1, 1);
        p1 += __shfl_xor_sync(0xffffffffu, p1, 2);

        // softmax over 16 k (k=g in p0, k=g+8 in p1); dup within quads is fine
        float mx = fmaxf(p0, p1);
        #pragma unroll
        for (int o = 4; o <= 16; o <<= 1)
            mx = fmaxf(mx, __shfl_xor_sync(0xffffffffu, mx, o));
        float e0v = __expf(p0 - mx);
        float e1v = __expf(p1 - mx);
        float s = e0v + e1v;
        #pragma unroll
        for (int o = 4; o <= 16; o <<= 1)
            s += __shfl_xor_sync(0xffffffffu, s, o);
        float a0n = e0v / s;
        float a1n = e1v / s;

        // broadcast alpha[k] via shfl (source lane 4*(k&7))
        float al2[KN];
        #pragma unroll
        for (int k = 0; k < 8; ++k)  al2[k]     = __shfl_sync(0xffffffffu, a0n, k << 2);
        #pragma unroll
        for (int k = 0; k < 8; ++k)  al2[k + 8] = __shfl_sync(0xffffffffu, a1n, k << 2);

        // ---- out[bn][d] = sum_k alpha[k] * neighbor[bn][k][d]  (re-read, L2 hot) ----
        {
            const float4* nb4 = (const float4*)nbase + lane;
            float4 acc = make_float4(0.f, 0.f, 0.f, 0.f);
            #pragma unroll
            for (int k = 0; k < KN; ++k) {
                float4 nv = nb4[k * 32];
                acc.x = fmaf(al2[k], nv.x, acc.x);
                acc.y = fmaf(al2[k], nv.y, acc.y);
                acc.z = fmaf(al2[k], nv.z, acc.z);
                acc.w = fmaf(al2[k], nv.w, acc.w);
            }
            ((float4*)(out + (size_t)bn * DIMX))[lane] = acc;
        }
    }
}

extern "C" void kernel_launch(void* const* d_in, const int* in_sizes, int n_in,
                              void* d_out, int out_size) {
    const float* neighbor = (const float*)d_in[1];
    const float* nweight  = (const float*)d_in[4];
    const float* extra    = (const float*)d_in[5];
    const float* w1       = (const float*)d_in[6];
    const float* w2       = (const float*)d_in[7];
    float* out            = (float*)d_out;

    const int total_bn = in_sizes[5] / DIMX;   // 65536

    cudaFuncSetAttribute(agg_mma_kernel, cudaFuncAttributeMaxDynamicSharedMemorySize, SM_TOTAL);
    agg_mma_kernel<<<304, NTHREADS, SM_TOTAL>>>(neighbor, nweight, extra, w1, w2, out, total_bn);
}